// round 7
// baseline (speedup 1.0000x reference)
#include <cuda_runtime.h>
#include <math.h>

#define Lc 8
#define Pc 8
#define Sc 128
#define Bc 16
#define Wc 768
#define Mc 64
#define W4   (Wc / 4)            // 192 float4 per W row == NTHR
#define ROW4 ((Bc * Wc) / 4)     // s-stride in float4 = 3072
#define NPROD (Lc * Pc * Bc)     // 1024 producer CTAs
#define NSEM  (Lc * Bc)          // 128 sem CTAs
#define NOUT  (Bc * 8)           // 128 out CTAs (b, m-group of 8)
#define NBLK  (NPROD + NSEM + NOUT)
#define NTHR  192

// Scratch (allocation-free device globals; zero-initialized at load)
__device__ float g_mp[Lc * Pc * Bc * Wc];   // [l,p,b,w] max over s (3 MB)
__device__ float g_score[Lc * Pc * Bc];     // raw score per (l,p,b)
__device__ float g_sem[Lc * Bc * Wc];       // [l,b,w] (384 KB)
__device__ unsigned g_flag[NPROD];          // producer done counters (monotonic)
__device__ unsigned g_semflag[NSEM];        // sem done counters (monotonic)
__device__ unsigned g_run_sem[NSEM];        // private run counters per sem CTA
__device__ unsigned g_run_out[NOUT];        // private run counters per out CTA

// ---------------------------------------------------------------------------
// One dataflow kernel. 1280 blocks x 192 threads. No global barrier.
// ---------------------------------------------------------------------------
__global__ __launch_bounds__(NTHR, 8)
void fused_kernel(const float* __restrict__ embeds,
                  const float* __restrict__ mask,
                  const float* __restrict__ w0,
                  const float* __restrict__ b0,
                  const float* __restrict__ w1,
                  const float* __restrict__ b1,
                  float* __restrict__ out)
{
    __shared__ float sw1[Sc];
    __shared__ float sred[6];
    __shared__ float s_misc[Lc * Pc];   // mask slice (out CTAs)
    __shared__ unsigned s_run;
    __shared__ float s_bias;

    const int t   = threadIdx.x;        // 0..191
    const int bid = blockIdx.x;

    if (t < Sc) sw1[t] = __ldg(w1 + t);
    __syncthreads();

    // ========================= PRODUCERS (bid < 1024) ======================
    if (bid < NPROD) {
        const int lpb = bid;             // (l*P+p)*B + b
        const int b   = lpb & (Bc - 1);
        const int lp  = lpb >> 4;

        const float4* base = reinterpret_cast<const float4*>(embeds)
                           + (size_t)lp * Sc * ROW4 + (size_t)b * W4 + t;
        const float4 w0v = __ldg(reinterpret_cast<const float4*>(w0) + t);

        float4 mx = make_float4(-3.4e38f, -3.4e38f, -3.4e38f, -3.4e38f);
        float dot0 = 0.0f, dot1 = 0.0f;

        #pragma unroll 8
        for (int s = 0; s < Sc; s += 2) {
            float4 v0 = __ldcs(base + (size_t)s * ROW4);
            float4 v1 = __ldcs(base + (size_t)(s + 1) * ROW4);
            mx.x = fmaxf(mx.x, fmaxf(v0.x, v1.x));
            mx.y = fmaxf(mx.y, fmaxf(v0.y, v1.y));
            mx.z = fmaxf(mx.z, fmaxf(v0.z, v1.z));
            mx.w = fmaxf(mx.w, fmaxf(v0.w, v1.w));
            dot0 += (v0.x * w0v.x + v0.y * w0v.y + v0.z * w0v.z + v0.w * w0v.w) * sw1[s];
            dot1 += (v1.x * w0v.x + v1.y * w0v.y + v1.z * w0v.z + v1.w * w0v.w) * sw1[s + 1];
        }

        __stcg(reinterpret_cast<float4*>(g_mp) + (size_t)lpb * W4 + t, mx);

        float dot = dot0 + dot1;
        #pragma unroll
        for (int o = 16; o > 0; o >>= 1)
            dot += __shfl_down_sync(0xffffffffu, dot, o);
        if ((t & 31) == 0) sred[t >> 5] = dot;
        __syncthreads();
        if (t == 0)
            __stcg(g_score + lpb, sred[0] + sred[1] + sred[2] + sred[3] + sred[4] + sred[5]);

        __syncthreads();                 // all mp stores issued before publish
        if (t == 0) {
            __threadfence();             // make mp/score visible GPU-wide
            atomicAdd(&g_flag[lpb], 1u); // publish (monotonic, replay-safe)
        }
        return;                          // free the SM immediately
    }

    // ========================= SEM CTAs (128): one per (l,b) ===============
    if (bid < NPROD + NSEM) {
        const int k = bid - NPROD;       // l*16 + b
        const int b = k & (Bc - 1);
        const int l = k >> 4;

        if (t == 0) {
            unsigned r = g_run_sem[k] + 1u;   // private counter: this run's target
            g_run_sem[k] = r;
            s_run = r;
            float s = 0.0f;
            #pragma unroll 8
            for (int i = 0; i < Sc; i++) s += sw1[i];
            s_bias = b0[0] * s + b1[0];
        }
        __syncthreads();
        const unsigned run = s_run;
        const float bias = s_bias;

        float4 acc = make_float4(0.f, 0.f, 0.f, 0.f);
        float  esum = 0.0f;

        #pragma unroll
        for (int p = 0; p < Pc; p++) {
            const int lpb = (l * Pc + p) * Bc + b;
            if (t == 0) {
                volatile unsigned* f = (volatile unsigned*)&g_flag[lpb];
                while (*f < run) __nanosleep(64);
                __threadfence();         // acquire producer's data
            }
            __syncthreads();
            float sc = __ldcg(g_score + lpb) + bias;
            float e  = __expf(1.0f / (1.0f + __expf(-sc)));   // exp(sigmoid)
            float4 m = __ldcg(reinterpret_cast<const float4*>(g_mp)
                              + (size_t)lpb * W4 + t);
            acc.x += e * m.x; acc.y += e * m.y;
            acc.z += e * m.z; acc.w += e * m.w;
            esum += e;
        }
        const float inv = 1.0f / esum;
        float4 sem = make_float4(acc.x * inv, acc.y * inv, acc.z * inv, acc.w * inv);
        __stcg(reinterpret_cast<float4*>(g_sem) + (size_t)k * W4 + t, sem);

        __syncthreads();
        if (t == 0) {
            __threadfence();
            atomicAdd(&g_semflag[k], 1u);
        }
        return;
    }

    // ========================= OUT CTAs (128): one per (b, m-group) ========
    {
        const int k  = bid - NPROD - NSEM;   // b*8 + mg
        const int mg = k & 7;
        const int b  = k >> 3;
        const int m0 = mg * 8;

        if (t == 0) {
            unsigned r = g_run_out[k] + 1u;
            g_run_out[k] = r;
            s_run = r;
        }
        // mask slice: s_misc[l*8+j] = mask[b, l, m0+j]
        if (t < 64) {
            const int l = t >> 3, j = t & 7;
            s_misc[t] = __ldg(mask + ((size_t)b * Lc + l) * Mc + m0 + j);
        }
        __syncthreads();
        const unsigned run = s_run;

        float4 o[8];
        #pragma unroll
        for (int j = 0; j < 8; j++) o[j] = make_float4(0.f, 0.f, 0.f, 0.f);

        #pragma unroll
        for (int l = 0; l < Lc; l++) {
            const int lb = l * Bc + b;
            if (t == 0) {
                volatile unsigned* f = (volatile unsigned*)&g_semflag[lb];
                while (*f < run) __nanosleep(64);
                __threadfence();
            }
            __syncthreads();
            float4 sv = __ldcg(reinterpret_cast<const float4*>(g_sem)
                               + (size_t)lb * W4 + t);
            #pragma unroll
            for (int j = 0; j < 8; j++) {
                const float mk = s_misc[l * 8 + j];
                o[j].x += mk * sv.x; o[j].y += mk * sv.y;
                o[j].z += mk * sv.z; o[j].w += mk * sv.w;
            }
        }
        #pragma unroll
        for (int j = 0; j < 8; j++)
            reinterpret_cast<float4*>(out)[((size_t)b * Mc + m0 + j) * W4 + t] = o[j];
    }
}

// ---------------------------------------------------------------------------
extern "C" void kernel_launch(void* const* d_in, const int* in_sizes, int n_in,
                              void* d_out, int out_size)
{
    const float* embeds = (const float*)d_in[0];  // [L,P,S,B,W]
    const float* mask   = (const float*)d_in[1];  // [B,L,M]
    const float* w0     = (const float*)d_in[2];  // [1,W]
    const float* b0     = (const float*)d_in[3];  // [1]
    const float* w1     = (const float*)d_in[4];  // [1,S]
    const float* b1     = (const float*)d_in[5];  // [1]
    float* out          = (float*)d_out;          // [B,M,W]

    fused_kernel<<<NBLK, NTHR>>>(embeds, mask, w0, b0, w1, b1, out);
}

// round 8
// speedup vs baseline: 1.1061x; 1.1061x over previous
#include <cuda_runtime.h>
#include <math.h>

#define Lc 8
#define Pc 8
#define Sc 128
#define Bc 16
#define Wc 768
#define Mc 64
#define W4   (Wc / 4)            // 192 float4 per W row == NTHR
#define ROW4 ((Bc * Wc) / 4)     // s-stride in float4 = 3072
#define NTHR 192

// Scratch (allocation-free: __device__ globals)
__device__ float g_mp[Lc * Pc * Bc * Wc];   // [l,p,b,w] max over s (3 MB)
__device__ float g_score[Lc * Pc * Bc];     // raw score per (l,p,b)

// ---------------------------------------------------------------------------
// Kernel 1: the PROVEN R2 streaming pass (61.8us standalone, 83.2% DRAM).
// 1024 blocks x 192 threads; thread t owns float4 column t, walks 128 s-rows.
// ---------------------------------------------------------------------------
__global__ __launch_bounds__(NTHR, 8)
void k1_pass(const float* __restrict__ embeds,
             const float* __restrict__ w0,
             const float* __restrict__ w1)
{
    __shared__ float sw1[Sc];
    __shared__ float sred[6];

    const int t = threadIdx.x;             // 0..191
    if (t < Sc) sw1[t] = __ldg(w1 + t);
    __syncthreads();

    const int lpb = blockIdx.x;            // (l*P + p)*B + b
    const int b   = lpb & (Bc - 1);
    const int lp  = lpb >> 4;

    const float4* base = reinterpret_cast<const float4*>(embeds)
                       + (size_t)lp * Sc * ROW4 + (size_t)b * W4 + t;
    const float4 w0v = __ldg(reinterpret_cast<const float4*>(w0) + t);

    float4 mx = make_float4(-3.4e38f, -3.4e38f, -3.4e38f, -3.4e38f);
    float dot = 0.0f;

    #pragma unroll 4
    for (int s = 0; s < Sc; s++) {
        float4 v = __ldg(base + (size_t)s * ROW4);
        mx.x = fmaxf(mx.x, v.x);
        mx.y = fmaxf(mx.y, v.y);
        mx.z = fmaxf(mx.z, v.z);
        mx.w = fmaxf(mx.w, v.w);
        dot += (v.x * w0v.x + v.y * w0v.y + v.z * w0v.z + v.w * w0v.w) * sw1[s];
    }

    reinterpret_cast<float4*>(g_mp)[(size_t)lpb * W4 + t] = mx;

    #pragma unroll
    for (int o = 16; o > 0; o >>= 1)
        dot += __shfl_down_sync(0xffffffffu, dot, o);
    if ((t & 31) == 0) sred[t >> 5] = dot;
    __syncthreads();
    if (t == 0)
        g_score[lpb] = sred[0] + sred[1] + sred[2] + sred[3] + sred[4] + sred[5];
}

// ---------------------------------------------------------------------------
// Kernel 2: fused epilogue. 128 CTAs, one per (b, m-group of 8).
// Recomputes the (trivial) softmax locally; sem[l] held in registers;
// emits 8 m-outputs per thread. All inputs are L2-resident after k1.
// ---------------------------------------------------------------------------
__global__ __launch_bounds__(NTHR)
void k_epi(const float* __restrict__ mask,
           const float* __restrict__ b0,
           const float* __restrict__ w1,
           const float* __restrict__ b1,
           float* __restrict__ out)
{
    __shared__ float s_soft[Lc * Pc];
    __shared__ float s_mask[Lc * Pc];
    __shared__ float s_bias;
    __shared__ float sw1[Sc];

    const int t  = threadIdx.x;
    const int b  = blockIdx.x & (Bc - 1);
    const int mg = blockIdx.x >> 4;                    // 0..7
    const int m0 = mg * 8;

    if (t < Sc) sw1[t] = __ldg(w1 + t);
    // mask slice: s_mask[l*8+j] = mask[b, l, m0+j]
    if (t >= 128) {
        const int k = t - 128;                         // 0..63
        const int l = k >> 3, j = k & 7;
        s_mask[k] = __ldg(mask + ((size_t)b * Lc + l) * Mc + m0 + j);
    }
    __syncthreads();
    if (t == 0) {
        float s = 0.0f;
        #pragma unroll 8
        for (int i = 0; i < Sc; i++) s += sw1[i];
        s_bias = b0[0] * s + b1[0];
    }
    __syncthreads();

    // softmax over p per l: threads 0..63 in 8-lane shfl groups
    if (t < 64) {
        const int l = t >> 3;
        const int p = t & 7;
        float r = __ldcg(g_score + (l * Pc + p) * Bc + b) + s_bias;
        r = 1.0f / (1.0f + __expf(-r));                // sigmoid
        float mxv = r;
        #pragma unroll
        for (int o = 4; o > 0; o >>= 1)
            mxv = fmaxf(mxv, __shfl_xor_sync(0xffffffffu, mxv, o));
        float e = __expf(r - mxv);
        float sum = e;
        #pragma unroll
        for (int o = 4; o > 0; o >>= 1)
            sum += __shfl_xor_sync(0xffffffffu, sum, o);
        s_soft[t] = e / sum;
    }
    __syncthreads();

    // sem_l[w4=t] in registers: 8 float4 accumulated over p (64 L2 loads)
    float4 sem[Lc];
    #pragma unroll
    for (int l = 0; l < Lc; l++) {
        float4 acc = make_float4(0.f, 0.f, 0.f, 0.f);
        #pragma unroll
        for (int p = 0; p < Pc; p++) {
            const float s = s_soft[l * Pc + p];
            float4 m = __ldcg(reinterpret_cast<const float4*>(g_mp)
                              + ((size_t)(l * Pc + p) * Bc + b) * W4 + t);
            acc.x += m.x * s; acc.y += m.y * s;
            acc.z += m.z * s; acc.w += m.w * s;
        }
        sem[l] = acc;
    }

    // 8 m-outputs per thread
    #pragma unroll
    for (int j = 0; j < 8; j++) {
        float4 acc = make_float4(0.f, 0.f, 0.f, 0.f);
        #pragma unroll
        for (int l = 0; l < Lc; l++) {
            const float mk = s_mask[l * 8 + j];
            acc.x += mk * sem[l].x; acc.y += mk * sem[l].y;
            acc.z += mk * sem[l].z; acc.w += mk * sem[l].w;
        }
        reinterpret_cast<float4*>(out)[((size_t)b * Mc + m0 + j) * W4 + t] = acc;
    }
}

// ---------------------------------------------------------------------------
extern "C" void kernel_launch(void* const* d_in, const int* in_sizes, int n_in,
                              void* d_out, int out_size)
{
    const float* embeds = (const float*)d_in[0];  // [L,P,S,B,W]
    const float* mask   = (const float*)d_in[1];  // [B,L,M]
    const float* w0     = (const float*)d_in[2];  // [1,W]
    const float* b0     = (const float*)d_in[3];  // [1]
    const float* w1     = (const float*)d_in[4];  // [1,S]
    const float* b1     = (const float*)d_in[5];  // [1]
    float* out          = (float*)d_out;          // [B,M,W]

    k1_pass<<<Lc * Pc * Bc, NTHR>>>(embeds, w0, w1);
    k_epi<<<Bc * 8, NTHR>>>(mask, b0, w1, b1, out);
}

// round 9
// speedup vs baseline: 1.1100x; 1.0035x over previous
#include <cuda_runtime.h>
#include <math.h>

#define Lc 8
#define Pc 8
#define Sc 128
#define Bc 16
#define Wc 768
#define Mc 64
#define W4   (Wc / 4)            // 192 float4 per W row == NTHR
#define ROW4 ((Bc * Wc) / 4)     // s-stride in float4 = 3072
#define NTHR 192
#define CK   12                  // float4 per epilogue w-chunk
#define NCHK (W4 / CK)           // 16 chunks

// Scratch (allocation-free: __device__ globals)
__device__ float g_mp[Lc * Pc * Bc * Wc];   // [l,p,b,w] max over s (3 MB)
__device__ float g_score[Lc * Pc * Bc];     // raw score per (l,p,b)

// ---------------------------------------------------------------------------
// Kernel 1: the PROVEN R2 streaming pass (61.8us standalone, 83.2% DRAM).
// 1024 blocks x 192 threads; thread t owns float4 column t, walks 128 s-rows.
// ---------------------------------------------------------------------------
__global__ __launch_bounds__(NTHR, 8)
void k1_pass(const float* __restrict__ embeds,
             const float* __restrict__ w0,
             const float* __restrict__ w1)
{
    __shared__ float sw1[Sc];
    __shared__ float sred[6];

    const int t = threadIdx.x;             // 0..191
    if (t < Sc) sw1[t] = __ldg(w1 + t);
    __syncthreads();

    const int lpb = blockIdx.x;            // (l*P + p)*B + b
    const int b   = lpb & (Bc - 1);
    const int lp  = lpb >> 4;

    const float4* base = reinterpret_cast<const float4*>(embeds)
                       + (size_t)lp * Sc * ROW4 + (size_t)b * W4 + t;
    const float4 w0v = __ldg(reinterpret_cast<const float4*>(w0) + t);

    float4 mx = make_float4(-3.4e38f, -3.4e38f, -3.4e38f, -3.4e38f);
    float dot = 0.0f;

    #pragma unroll 4
    for (int s = 0; s < Sc; s++) {
        float4 v = __ldg(base + (size_t)s * ROW4);
        mx.x = fmaxf(mx.x, v.x);
        mx.y = fmaxf(mx.y, v.y);
        mx.z = fmaxf(mx.z, v.z);
        mx.w = fmaxf(mx.w, v.w);
        dot += (v.x * w0v.x + v.y * w0v.y + v.z * w0v.z + v.w * w0v.w) * sw1[s];
    }

    reinterpret_cast<float4*>(g_mp)[(size_t)lpb * W4 + t] = mx;

    #pragma unroll
    for (int o = 16; o > 0; o >>= 1)
        dot += __shfl_down_sync(0xffffffffu, dot, o);
    if ((t & 31) == 0) sred[t >> 5] = dot;
    __syncthreads();
    if (t == 0)
        g_score[lpb] = sred[0] + sred[1] + sred[2] + sred[3] + sred[4] + sred[5];
}

// ---------------------------------------------------------------------------
// Kernel 2: epilogue with smem-staged sem. 256 CTAs = (b, chunk of 12 float4).
// g_mp is read exactly ONCE kernel-wide (3 MB). Per CTA:
//   s_mask[512]  <- mask[b,:,:]  (contiguous)
//   s_soft[64]   <- sigmoid+softmax over p per l (shfl groups)
//   s_sem[l][k]  <- sum_p soft * mp   (96 threads, 8-deep MLP)
//   out          <- 64 m x 12 float4  (192 threads x 4, smem FMAs)
// ---------------------------------------------------------------------------
__global__ __launch_bounds__(NTHR)
void k_epi(const float* __restrict__ mask,
           const float* __restrict__ b0,
           const float* __restrict__ w1,
           const float* __restrict__ b1,
           float* __restrict__ out)
{
    __shared__ float  sw1[Sc];
    __shared__ float  s_mask[Lc * Mc];      // 512 floats = mask[b,:,:]
    __shared__ float  s_soft[Lc * Pc];
    __shared__ float  s_bias;
    __shared__ float4 s_sem[Lc][CK];

    const int t     = threadIdx.x;          // 0..191
    const int b     = blockIdx.x >> 4;
    const int chunk = blockIdx.x & (NCHK - 1);
    const int wbase = chunk * CK;            // float4 offset within W4

    if (t < Sc) sw1[t] = __ldg(w1 + t);
    #pragma unroll
    for (int i = t; i < Lc * Mc; i += NTHR)
        s_mask[i] = __ldg(mask + (size_t)b * Lc * Mc + i);
    __syncthreads();

    if (t == 0) {
        float s = 0.0f;
        #pragma unroll 8
        for (int i = 0; i < Sc; i++) s += sw1[i];
        s_bias = b0[0] * s + b1[0];
    }
    __syncthreads();

    // softmax over p per l: threads 0..63 in 8-lane shfl groups
    if (t < 64) {
        const int l = t >> 3;
        const int p = t & 7;
        float r = __ldcg(g_score + (l * Pc + p) * Bc + b) + s_bias;
        r = 1.0f / (1.0f + __expf(-r));      // sigmoid
        float mxv = r;
        #pragma unroll
        for (int o = 4; o > 0; o >>= 1)
            mxv = fmaxf(mxv, __shfl_xor_sync(0xffffffffu, mxv, o));
        float e = __expf(r - mxv);
        float sum = e;
        #pragma unroll
        for (int o = 4; o > 0; o >>= 1)
            sum += __shfl_xor_sync(0xffffffffu, sum, o);
        s_soft[t] = e / sum;
    }
    __syncthreads();

    // sem[l][k] = sum_p soft[l,p] * mp[l,p,b, wbase+k]   (96 threads, 8 loads)
    if (t < Lc * CK) {
        const int l = t / CK;
        const int k = t % CK;
        float4 acc = make_float4(0.f, 0.f, 0.f, 0.f);
        #pragma unroll
        for (int p = 0; p < Pc; p++) {
            const float s = s_soft[l * Pc + p];
            float4 m = __ldcg(reinterpret_cast<const float4*>(g_mp)
                              + ((size_t)(l * Pc + p) * Bc + b) * W4 + wbase + k);
            acc.x += s * m.x; acc.y += s * m.y;
            acc.z += s * m.z; acc.w += s * m.w;
        }
        s_sem[l][k] = acc;
    }
    __syncthreads();

    // out[b, m, wbase+k] = sum_l mask[b,l,m] * sem[l][k]  (768 outputs, 4/thread)
    #pragma unroll
    for (int i = t; i < Mc * CK; i += NTHR) {
        const int m = i / CK;
        const int k = i % CK;
        float4 acc = make_float4(0.f, 0.f, 0.f, 0.f);
        #pragma unroll
        for (int l = 0; l < Lc; l++) {
            const float mk = s_mask[l * Mc + m];
            float4 sv = s_sem[l][k];
            acc.x += mk * sv.x; acc.y += mk * sv.y;
            acc.z += mk * sv.z; acc.w += mk * sv.w;
        }
        reinterpret_cast<float4*>(out)[((size_t)b * Mc + m) * W4 + wbase + k] = acc;
    }
}

// ---------------------------------------------------------------------------
extern "C" void kernel_launch(void* const* d_in, const int* in_sizes, int n_in,
                              void* d_out, int out_size)
{
    const float* embeds = (const float*)d_in[0];  // [L,P,S,B,W]
    const float* mask   = (const float*)d_in[1];  // [B,L,M]
    const float* w0     = (const float*)d_in[2];  // [1,W]
    const float* b0     = (const float*)d_in[3];  // [1]
    const float* w1     = (const float*)d_in[4];  // [1,S]
    const float* b1     = (const float*)d_in[5];  // [1]
    float* out          = (float*)d_out;          // [B,M,W]

    k1_pass<<<Lc * Pc * Bc, NTHR>>>(embeds, w0, w1);
    k_epi<<<Bc * NCHK, NTHR>>>(mask, b0, w1, b1, out);
}

// round 10
// speedup vs baseline: 1.1491x; 1.0352x over previous
#include <cuda_runtime.h>
#include <math.h>

#define Lc 8
#define Pc 8
#define Sc 128
#define Bc 16
#define Wc 768
#define Mc 64
#define W4   (Wc / 4)            // 192 float4 per W row == NTHR
#define ROW4 ((Bc * Wc) / 4)     // s-stride in float4 = 3072
#define NTHR 192
#define CK   12                  // float4 per epilogue w-chunk
#define NCHK (W4 / CK)           // 16 chunks -> 256 epilogue CTAs

// Scratch (allocation-free: __device__ globals)
__device__ float g_mp[Lc * Pc * Bc * Wc];   // [l,p,b,w] max over s (3 MB)
__device__ float g_score[Lc * Pc * Bc];     // raw score per (l,p,b)
__device__ float g_bias;                    // b0*sum(w1)+b1

// ---------------------------------------------------------------------------
// Kernel 1: proven streaming pass, with __ldcs (evict-first) so the 402 MB
// embeds stream does NOT evict g_mp/g_score from L2 (k_epi needs them hot).
// 1024 blocks x 192 threads; thread t owns float4 column t, walks 128 s-rows.
// ---------------------------------------------------------------------------
__global__ __launch_bounds__(NTHR, 8)
void k1_pass(const float* __restrict__ embeds,
             const float* __restrict__ w0,
             const float* __restrict__ w1,
             const float* __restrict__ b0,
             const float* __restrict__ b1)
{
    __shared__ float sw1[Sc];
    __shared__ float sred[6];

    const int t = threadIdx.x;             // 0..191
    if (t < Sc) sw1[t] = __ldg(w1 + t);
    __syncthreads();

    const int lpb = blockIdx.x;            // (l*P + p)*B + b
    const int b   = lpb & (Bc - 1);
    const int lp  = lpb >> 4;

    const float4* base = reinterpret_cast<const float4*>(embeds)
                       + (size_t)lp * Sc * ROW4 + (size_t)b * W4 + t;
    const float4 w0v = __ldg(reinterpret_cast<const float4*>(w0) + t);

    float4 mx = make_float4(-3.4e38f, -3.4e38f, -3.4e38f, -3.4e38f);
    float dot = 0.0f;

    #pragma unroll 4
    for (int s = 0; s < Sc; s++) {
        float4 v = __ldcs(base + (size_t)s * ROW4);   // streaming: evict-first
        mx.x = fmaxf(mx.x, v.x);
        mx.y = fmaxf(mx.y, v.y);
        mx.z = fmaxf(mx.z, v.z);
        mx.w = fmaxf(mx.w, v.w);
        dot += (v.x * w0v.x + v.y * w0v.y + v.z * w0v.z + v.w * w0v.w) * sw1[s];
    }

    reinterpret_cast<float4*>(g_mp)[(size_t)lpb * W4 + t] = mx;

    #pragma unroll
    for (int o = 16; o > 0; o >>= 1)
        dot += __shfl_down_sync(0xffffffffu, dot, o);
    if ((t & 31) == 0) sred[t >> 5] = dot;
    __syncthreads();
    if (t == 0)
        g_score[lpb] = sred[0] + sred[1] + sred[2] + sred[3] + sred[4] + sred[5];

    // bias hoisted out of the epilogue critical path (block 0, off to the side)
    if (lpb == 0 && t == 1) {
        float s = 0.0f;
        #pragma unroll 8
        for (int i = 0; i < Sc; i++) s += sw1[i];
        g_bias = b0[0] * s + b1[0];
    }
}

// ---------------------------------------------------------------------------
// Kernel 2: load-first epilogue. 256 CTAs = (b, w-chunk of 12 float4).
// Thread t = (l, k, h): l = t/24, k = (t%24)>>1, h = t&1 (p-half).
// Step 1 (instr 0): issue 4 independent mp float4 loads  <- overlaps all else
// Step 2: mask -> smem; threads 0..63 do score->sigmoid->softmax (shfl)
// Step 3: partial sem over p-half -> smem
// Step 4: 4 outputs/thread: out[b,m,k] = sum_l mask*(half0+half1)
// ---------------------------------------------------------------------------
__global__ __launch_bounds__(NTHR)
void k_epi(const float* __restrict__ mask,
           float* __restrict__ out)
{
    __shared__ float  s_mask[Lc * Mc];       // 512 floats = mask[b,:,:]
    __shared__ float  s_soft[Lc * Pc];
    __shared__ float4 s_part[Lc][CK][2];     // partial sem halves (3 KB)

    const int t     = threadIdx.x;           // 0..191
    const int b     = blockIdx.x >> 4;
    const int chunk = blockIdx.x & (NCHK - 1);
    const int wbase = chunk * CK;             // float4 offset within W4

    const int l = t / (CK * 2);               // 0..7
    const int r = t % (CK * 2);
    const int k = r >> 1;                     // 0..11
    const int h = r & 1;                      // p-half

    // ---- Step 1: fire the latency-critical mp loads immediately ----------
    float4 mpv[4];
    #pragma unroll
    for (int q = 0; q < 4; q++) {
        const int p = h * 4 + q;
        mpv[q] = __ldcg(reinterpret_cast<const float4*>(g_mp)
                        + ((size_t)(l * Pc + p) * Bc + b) * W4 + wbase + k);
    }

    // ---- Step 2: mask -> smem (overlapped with mp loads in flight) -------
    #pragma unroll
    for (int i = t; i < Lc * Mc; i += NTHR)
        s_mask[i] = __ldg(mask + (size_t)b * Lc * Mc + i);

    // softmax over p per l: threads 0..63 in 8-lane shfl groups
    if (t < 64) {
        const int sl = t >> 3;
        const int sp = t & 7;
        float rr = __ldcg(g_score + (sl * Pc + sp) * Bc + b) + g_bias;
        rr = 1.0f / (1.0f + __expf(-rr));      // sigmoid
        float mxv = rr;
        #pragma unroll
        for (int o = 4; o > 0; o >>= 1)
            mxv = fmaxf(mxv, __shfl_xor_sync(0xffffffffu, mxv, o));
        float e = __expf(rr - mxv);
        float sum = e;
        #pragma unroll
        for (int o = 4; o > 0; o >>= 1)
            sum += __shfl_xor_sync(0xffffffffu, sum, o);
        s_soft[t] = e / sum;
    }
    __syncthreads();

    // ---- Step 3: partial sem over this thread's p-half -------------------
    {
        float4 acc = make_float4(0.f, 0.f, 0.f, 0.f);
        #pragma unroll
        for (int q = 0; q < 4; q++) {
            const float s = s_soft[l * Pc + h * 4 + q];
            acc.x += s * mpv[q].x; acc.y += s * mpv[q].y;
            acc.z += s * mpv[q].z; acc.w += s * mpv[q].w;
        }
        s_part[l][k][h] = acc;
    }
    __syncthreads();

    // ---- Step 4: out[b, m, wbase+k] = sum_l mask[b,l,m] * sem[l][k] -------
    #pragma unroll
    for (int i = t; i < Mc * CK; i += NTHR) {
        const int m  = i / CK;
        const int kk = i % CK;
        float4 acc = make_float4(0.f, 0.f, 0.f, 0.f);
        #pragma unroll
        for (int ll = 0; ll < Lc; ll++) {
            const float mk = s_mask[ll * Mc + m];
            float4 a = s_part[ll][kk][0];
            float4 c = s_part[ll][kk][1];
            acc.x += mk * (a.x + c.x); acc.y += mk * (a.y + c.y);
            acc.z += mk * (a.z + c.z); acc.w += mk * (a.w + c.w);
        }
        reinterpret_cast<float4*>(out)[((size_t)b * Mc + m) * W4 + wbase + kk] = acc;
    }
}

// ---------------------------------------------------------------------------
extern "C" void kernel_launch(void* const* d_in, const int* in_sizes, int n_in,
                              void* d_out, int out_size)
{
    const float* embeds = (const float*)d_in[0];  // [L,P,S,B,W]
    const float* mask   = (const float*)d_in[1];  // [B,L,M]
    const float* w0     = (const float*)d_in[2];  // [1,W]
    const float* b0     = (const float*)d_in[3];  // [1]
    const float* w1     = (const float*)d_in[4];  // [1,S]
    const float* b1     = (const float*)d_in[5];  // [1]
    float* out          = (float*)d_out;          // [B,M,W]

    k1_pass<<<Lc * Pc * Bc, NTHR>>>(embeds, w0, w1, b0, b1);
    k_epi<<<Bc * NCHK, NTHR>>>(mask, out);
}